// round 10
// baseline (speedup 1.0000x reference)
#include <cuda_runtime.h>
#include <math.h>

// Problem constants
#define B_    32
#define T_    512
#define HID_  1024
#define G4    4096      // 4*HID
#define NCTA  128       // persistent CTAs (<= SM count, all co-resident)

// ---------------------------------------------------------------------------
// Device scratch (no allocation allowed -> __device__ globals)
// ---------------------------------------------------------------------------
__device__ float    g_xg[(size_t)B_ * T_ * G4];   // [B][T][4H] input projections (268 MB)
__device__ float    g_h[2][B_ * HID_];            // double-buffered hidden state [b][j]
__device__ unsigned g_bar_cnt;                    // grid barrier state (self-resetting)
__device__ unsigned g_bar_gen;

// ---------------------------------------------------------------------------
// Software grid barrier (all NCTA CTAs co-resident => no deadlock)
// ---------------------------------------------------------------------------
__device__ __forceinline__ void grid_barrier(unsigned nb) {
    __syncthreads();
    if (threadIdx.x == 0) {
        volatile unsigned* vgen = &g_bar_gen;
        unsigned gen = *vgen;
        __threadfence();
        if (atomicAdd(&g_bar_cnt, 1u) == nb - 1u) {
            g_bar_cnt = 0u;
            __threadfence();
            *vgen = gen + 1u;
        } else {
            while (*vgen == gen) { }
            __threadfence();
        }
    }
    __syncthreads();
}

// ---------------------------------------------------------------------------
// init: h[0] <- h0
// ---------------------------------------------------------------------------
__global__ void init_h_kernel(const float* __restrict__ h0) {
    int i = blockIdx.x * blockDim.x + threadIdx.x;
    if (i < B_ * HID_) g_h[0][i] = h0[i];
}

// ---------------------------------------------------------------------------
// Phase 1: xg[m][n] = sum_k x[m][k] * W_ih[n][k] + b_ih[n] + b_hh[n]
// M=16384 (m = b*T+t), N=4096, K=1024. Classic 128x128x16 SGEMM-NT, 8x8 micro.
// ---------------------------------------------------------------------------
#define BM 128
#define BN 128
#define BK 16

__global__ __launch_bounds__(256) void xg_gemm_kernel(
    const float* __restrict__ x, const float* __restrict__ Wih,
    const float* __restrict__ bih, const float* __restrict__ bhh)
{
    __shared__ float As[BK][BM + 4];
    __shared__ float Bs[BK][BN + 4];

    const int m0 = blockIdx.y * BM;
    const int n0 = blockIdx.x * BN;
    const int tid = threadIdx.x;
    const int tx = tid & 15;        // 0..15 -> cols tx*8..+7
    const int ty = tid >> 4;        // 0..15 -> rows ty*8..+7
    const int lrow = tid >> 2;      // 0..63
    const int lcol = (tid & 3) << 2;// 0,4,8,12

    float acc[8][8];
    #pragma unroll
    for (int i = 0; i < 8; ++i)
        #pragma unroll
        for (int j = 0; j < 8; ++j) acc[i][j] = 0.0f;

    for (int kc = 0; kc < 1024; kc += BK) {
        // stage loads in registers (overlaps the sync below)
        float4 a0 = *(const float4*)(x   + (size_t)(m0 + lrow)      * 1024 + kc + lcol);
        float4 a1 = *(const float4*)(x   + (size_t)(m0 + lrow + 64) * 1024 + kc + lcol);
        float4 b0 = *(const float4*)(Wih + (size_t)(n0 + lrow)      * 1024 + kc + lcol);
        float4 b1 = *(const float4*)(Wih + (size_t)(n0 + lrow + 64) * 1024 + kc + lcol);
        __syncthreads();   // previous iteration's compute done -> smem reusable
        As[lcol + 0][lrow] = a0.x; As[lcol + 1][lrow] = a0.y;
        As[lcol + 2][lrow] = a0.z; As[lcol + 3][lrow] = a0.w;
        As[lcol + 0][lrow + 64] = a1.x; As[lcol + 1][lrow + 64] = a1.y;
        As[lcol + 2][lrow + 64] = a1.z; As[lcol + 3][lrow + 64] = a1.w;
        Bs[lcol + 0][lrow] = b0.x; Bs[lcol + 1][lrow] = b0.y;
        Bs[lcol + 2][lrow] = b0.z; Bs[lcol + 3][lrow] = b0.w;
        Bs[lcol + 0][lrow + 64] = b1.x; Bs[lcol + 1][lrow + 64] = b1.y;
        Bs[lcol + 2][lrow + 64] = b1.z; Bs[lcol + 3][lrow + 64] = b1.w;
        __syncthreads();

        #pragma unroll
        for (int k = 0; k < BK; ++k) {
            float ar[8], br[8];
            float4 va0 = *(const float4*)&As[k][ty * 8];
            float4 va1 = *(const float4*)&As[k][ty * 8 + 4];
            float4 vb0 = *(const float4*)&Bs[k][tx * 8];
            float4 vb1 = *(const float4*)&Bs[k][tx * 8 + 4];
            ar[0] = va0.x; ar[1] = va0.y; ar[2] = va0.z; ar[3] = va0.w;
            ar[4] = va1.x; ar[5] = va1.y; ar[6] = va1.z; ar[7] = va1.w;
            br[0] = vb0.x; br[1] = vb0.y; br[2] = vb0.z; br[3] = vb0.w;
            br[4] = vb1.x; br[5] = vb1.y; br[6] = vb1.z; br[7] = vb1.w;
            #pragma unroll
            for (int i = 0; i < 8; ++i)
                #pragma unroll
                for (int j = 0; j < 8; ++j)
                    acc[i][j] = fmaf(ar[i], br[j], acc[i][j]);
        }
    }

    // epilogue: + (b_ih + b_hh), write [m][n]
    float bias[8];
    #pragma unroll
    for (int j = 0; j < 8; ++j) {
        int n = n0 + tx * 8 + j;
        bias[j] = bih[n] + bhh[n];
    }
    #pragma unroll
    for (int i = 0; i < 8; ++i) {
        size_t o = (size_t)(m0 + ty * 8 + i) * G4 + n0 + tx * 8;
        float4 v0, v1;
        v0.x = acc[i][0] + bias[0]; v0.y = acc[i][1] + bias[1];
        v0.z = acc[i][2] + bias[2]; v0.w = acc[i][3] + bias[3];
        v1.x = acc[i][4] + bias[4]; v1.y = acc[i][5] + bias[5];
        v1.z = acc[i][6] + bias[6]; v1.w = acc[i][7] + bias[7];
        *(float4*)(g_xg + o)     = v0;
        *(float4*)(g_xg + o + 4) = v1;
    }
}

// ---------------------------------------------------------------------------
// Phase 2: persistent recurrent kernel. 128 CTAs, CTA b owns hidden units
// j0=8b..8b+7 => gate rows {q*1024 + j0 + jj}, q=0..3. Its 32x1024 W_hh slice
// stays in SMEM for all 512 steps; c stays in SMEM; only h goes through L2.
// ---------------------------------------------------------------------------
#define WPAD 34
#define HPAD 34
#define KC   64
#define SM_WSZ   (1024 * WPAD)     // Wsm floats
#define SM_HSZ   (2 * KC * HPAD)   // hsm floats (double buffer)
#define SM_GSZ   (32 * 33)         // gates
#define SM_CSZ   (8 * 33)          // cell state
#define SMEM_REC ((SM_WSZ + SM_HSZ + SM_GSZ + SM_CSZ) * sizeof(float))

__global__ __launch_bounds__(256, 1) void lstm_rec_kernel(
    const float* __restrict__ Whh, const float* __restrict__ c0)
{
    extern __shared__ float sm[];
    float* Wsm = sm;                    // [1024][WPAD], Wsm[k*WPAD+r] = W_hh[row(r)][k]
    float* hsm = Wsm + SM_WSZ;          // [2][KC][HPAD], hsm[k*HPAD+b] = h[b][k]
    float* gsm = hsm + SM_HSZ;          // [32][33] raw gate pre-acts
    float* csm = gsm + SM_GSZ;          // [8][33]  cell state

    const int tid = threadIdx.x;
    const int bid = blockIdx.x;
    const int j0  = bid * 8;

    // load W_hh slice (once), k-fast-in-global -> coalesced
    for (int idx = tid; idx < 32 * 1024; idx += 256) {
        int r = idx >> 10;              // 0..31 (gate-major: r = q*8+jj)
        int k = idx & 1023;
        int q = r >> 3, jj = r & 7;
        Wsm[k * WPAD + r] = Whh[(size_t)(q * HID_ + j0 + jj) * HID_ + k];
    }
    // init cell state
    const int je = tid & 7;             // elementwise mapping: lane-fast over j
    const int be = tid >> 3;
    csm[je * 33 + be] = c0[be * HID_ + j0 + je];
    __syncthreads();

    const int rt = tid >> 4;            // rows 2rt, 2rt+1
    const int bt = tid & 15;            // batches 2bt, 2bt+1

    for (int t = 0; t < T_; ++t) {
        const float* hg = g_h[t & 1];
        float*       hw = g_h[(t & 1) ^ 1];
        float a00 = 0.f, a01 = 0.f, a10 = 0.f, a11 = 0.f;

        // prefetch chunk 0 (k = 0..63), __ldcg: h written by other SMs this launch
        #pragma unroll
        for (int i = 0; i < 8; ++i) {
            int idx = tid + (i << 8);
            int bb = idx >> 6, kk = idx & 63;
            hsm[kk * HPAD + bb] = __ldcg(hg + bb * HID_ + kk);
        }

        #pragma unroll 1
        for (int c = 0; c < 16; ++c) {
            __syncthreads();            // chunk c staged; other buffer free
            if (c + 1 < 16) {
                float* dst = hsm + ((c + 1) & 1) * (KC * HPAD);
                int kb = (c + 1) << 6;
                #pragma unroll
                for (int i = 0; i < 8; ++i) {
                    int idx = tid + (i << 8);
                    int bb = idx >> 6, kk = idx & 63;
                    dst[kk * HPAD + bb] = __ldcg(hg + bb * HID_ + kb + kk);
                }
            }
            const float* hb = hsm + (c & 1) * (KC * HPAD);
            const float* wb = Wsm + (c << 6) * WPAD;
            #pragma unroll
            for (int k = 0; k < KC; ++k) {
                float2 w  = *(const float2*)(wb + k * WPAD + (rt << 1));
                float2 hv = *(const float2*)(hb + k * HPAD + (bt << 1));
                a00 = fmaf(w.x, hv.x, a00);
                a01 = fmaf(w.x, hv.y, a01);
                a10 = fmaf(w.y, hv.x, a10);
                a11 = fmaf(w.y, hv.y, a11);
            }
        }
        __syncthreads();
        gsm[(rt * 2 + 0) * 33 + bt * 2 + 0] = a00;
        gsm[(rt * 2 + 0) * 33 + bt * 2 + 1] = a01;
        gsm[(rt * 2 + 1) * 33 + bt * 2 + 0] = a10;
        gsm[(rt * 2 + 1) * 33 + bt * 2 + 1] = a11;
        __syncthreads();

        // elementwise LSTM cell: thread (je, be); xg read lane-fast over j
        {
            const int mbase = ((be * T_ + t) << 12) + j0 + je;  // (b*T+t)*4096 + ...
            float pi = gsm[(0 * 8 + je) * 33 + be] + g_xg[mbase];
            float pf = gsm[(1 * 8 + je) * 33 + be] + g_xg[mbase + 1024];
            float pg = gsm[(2 * 8 + je) * 33 + be] + g_xg[mbase + 2048];
            float po = gsm[(3 * 8 + je) * 33 + be] + g_xg[mbase + 3072];
            float ig = 1.0f / (1.0f + expf(-pi));
            float fg = 1.0f / (1.0f + expf(-pf));
            float gg = tanhf(pg);
            float og = 1.0f / (1.0f + expf(-po));
            float cn = fmaf(fg, csm[je * 33 + be], ig * gg);
            csm[je * 33 + be] = cn;
            hw[be * HID_ + j0 + je] = og * tanhf(cn);
        }
        grid_barrier(NCTA);
    }
    // after t=511 (odd), final h is in g_h[0]
}

// ---------------------------------------------------------------------------
// final copy: d_out <- g_h[0]
// ---------------------------------------------------------------------------
__global__ void copy_out_kernel(float* __restrict__ out) {
    int i = blockIdx.x * blockDim.x + threadIdx.x;
    if (i < B_ * HID_) out[i] = g_h[0][i];
}

// ---------------------------------------------------------------------------
// launch
// ---------------------------------------------------------------------------
extern "C" void kernel_launch(void* const* d_in, const int* in_sizes, int n_in,
                              void* d_out, int out_size) {
    const float* x   = (const float*)d_in[0];
    const float* h0  = (const float*)d_in[1];
    const float* c0  = (const float*)d_in[2];
    const float* Wih = (const float*)d_in[3];
    const float* Whh = (const float*)d_in[4];
    const float* bih = (const float*)d_in[5];
    const float* bhh = (const float*)d_in[6];
    float* out = (float*)d_out;

    cudaFuncSetAttribute(lstm_rec_kernel,
                         cudaFuncAttributeMaxDynamicSharedMemorySize,
                         (int)SMEM_REC);

    init_h_kernel<<<32, 1024>>>(h0);

    dim3 grid(G4 / BN, (B_ * T_) / BM);   // 32 x 128 CTAs
    xg_gemm_kernel<<<grid, 256>>>(x, Wih, bih, bhh);

    lstm_rec_kernel<<<NCTA, 256, SMEM_REC>>>(Whh, c0);

    copy_out_kernel<<<32, 1024>>>(out);
}

// round 11
// speedup vs baseline: 1.4333x; 1.4333x over previous
#include <cuda_runtime.h>
#include <math.h>

// Problem constants
#define B_    32
#define T_    512
#define HID_  1024
#define G4    4096
#define NCTA  128

typedef unsigned long long ull;

// ---------------------------------------------------------------------------
// f32x2 packed-math helpers (sm_100+): one FFMA2 = 2 fp32 FMA lanes
// ---------------------------------------------------------------------------
__device__ __forceinline__ void ffma2(ull& d, ull a, ull b) {
    asm("fma.rn.f32x2 %0, %1, %2, %0;" : "+l"(d) : "l"(a), "l"(b));
}
__device__ __forceinline__ ull pack2(float x) {
    ull r;
    asm("mov.b64 %0, {%1, %1};" : "=l"(r) : "r"(__float_as_uint(x)));
    return r;
}
__device__ __forceinline__ float2 unpack2(ull v) {
    unsigned lo, hi;
    asm("mov.b64 {%0, %1}, %2;" : "=r"(lo), "=r"(hi) : "l"(v));
    return make_float2(__uint_as_float(lo), __uint_as_float(hi));
}

// ---------------------------------------------------------------------------
// Device scratch
// ---------------------------------------------------------------------------
__device__ float    g_xg[(size_t)B_ * T_ * G4];   // [B][T][4H]
__device__ float    g_h[2][B_ * HID_];            // double-buffered h
__device__ unsigned g_bar_cnt;
__device__ unsigned g_bar_gen;

// ---------------------------------------------------------------------------
// Software grid barrier (all NCTA CTAs co-resident)
// ---------------------------------------------------------------------------
__device__ __forceinline__ void grid_barrier(unsigned nb) {
    __syncthreads();
    if (threadIdx.x == 0) {
        volatile unsigned* vgen = &g_bar_gen;
        unsigned gen = *vgen;
        __threadfence();
        if (atomicAdd(&g_bar_cnt, 1u) == nb - 1u) {
            g_bar_cnt = 0u;
            __threadfence();
            *vgen = gen + 1u;
        } else {
            while (*vgen == gen) { }
            __threadfence();
        }
    }
    __syncthreads();
}

__global__ void init_h_kernel(const float* __restrict__ h0) {
    int i = blockIdx.x * blockDim.x + threadIdx.x;
    if (i < B_ * HID_) g_h[0][i] = h0[i];
}

// ---------------------------------------------------------------------------
// Phase 1: xg = x @ W_ih^T + (b_ih + b_hh). 128x128x16 tiles, 8x8 micro, FFMA2.
// ---------------------------------------------------------------------------
#define BM 128
#define BN 128
#define BK 16

__global__ __launch_bounds__(256) void xg_gemm_kernel(
    const float* __restrict__ x, const float* __restrict__ Wih,
    const float* __restrict__ bih, const float* __restrict__ bhh)
{
    __shared__ __align__(16) float As[BK][BM + 4];
    __shared__ __align__(16) float Bs[BK][BN + 4];

    const int m0 = blockIdx.y * BM;
    const int n0 = blockIdx.x * BN;
    const int tid = threadIdx.x;
    const int tx = tid & 15;
    const int ty = tid >> 4;
    const int lrow = tid >> 2;
    const int lcol = (tid & 3) << 2;

    ull acc[8][4];
    #pragma unroll
    for (int i = 0; i < 8; ++i)
        #pragma unroll
        for (int j = 0; j < 4; ++j) acc[i][j] = 0ull;

    for (int kc = 0; kc < 1024; kc += BK) {
        float4 a0 = *(const float4*)(x   + (size_t)(m0 + lrow)      * 1024 + kc + lcol);
        float4 a1 = *(const float4*)(x   + (size_t)(m0 + lrow + 64) * 1024 + kc + lcol);
        float4 b0 = *(const float4*)(Wih + (size_t)(n0 + lrow)      * 1024 + kc + lcol);
        float4 b1 = *(const float4*)(Wih + (size_t)(n0 + lrow + 64) * 1024 + kc + lcol);
        __syncthreads();
        As[lcol + 0][lrow] = a0.x; As[lcol + 1][lrow] = a0.y;
        As[lcol + 2][lrow] = a0.z; As[lcol + 3][lrow] = a0.w;
        As[lcol + 0][lrow + 64] = a1.x; As[lcol + 1][lrow + 64] = a1.y;
        As[lcol + 2][lrow + 64] = a1.z; As[lcol + 3][lrow + 64] = a1.w;
        Bs[lcol + 0][lrow] = b0.x; Bs[lcol + 1][lrow] = b0.y;
        Bs[lcol + 2][lrow] = b0.z; Bs[lcol + 3][lrow] = b0.w;
        Bs[lcol + 0][lrow + 64] = b1.x; Bs[lcol + 1][lrow + 64] = b1.y;
        Bs[lcol + 2][lrow + 64] = b1.z; Bs[lcol + 3][lrow + 64] = b1.w;
        __syncthreads();

        #pragma unroll
        for (int k = 0; k < BK; ++k) {
            float4 va0 = *(const float4*)&As[k][ty * 8];
            float4 va1 = *(const float4*)&As[k][ty * 8 + 4];
            ulonglong2 vb0 = *(const ulonglong2*)&Bs[k][tx * 8];      // (b0,b1),(b2,b3)
            ulonglong2 vb1 = *(const ulonglong2*)&Bs[k][tx * 8 + 4];  // (b4,b5),(b6,b7)
            float ar[8] = {va0.x, va0.y, va0.z, va0.w, va1.x, va1.y, va1.z, va1.w};
            #pragma unroll
            for (int i = 0; i < 8; ++i) {
                ull pa = pack2(ar[i]);
                ffma2(acc[i][0], pa, vb0.x);
                ffma2(acc[i][1], pa, vb0.y);
                ffma2(acc[i][2], pa, vb1.x);
                ffma2(acc[i][3], pa, vb1.y);
            }
        }
    }

    float bias[8];
    #pragma unroll
    for (int j = 0; j < 8; ++j) {
        int n = n0 + tx * 8 + j;
        bias[j] = bih[n] + bhh[n];
    }
    #pragma unroll
    for (int i = 0; i < 8; ++i) {
        float2 c0 = unpack2(acc[i][0]);
        float2 c1 = unpack2(acc[i][1]);
        float2 c2 = unpack2(acc[i][2]);
        float2 c3 = unpack2(acc[i][3]);
        size_t o = (size_t)(m0 + ty * 8 + i) * G4 + n0 + tx * 8;
        float4 v0, v1;
        v0.x = c0.x + bias[0]; v0.y = c0.y + bias[1];
        v0.z = c1.x + bias[2]; v0.w = c1.y + bias[3];
        v1.x = c2.x + bias[4]; v1.y = c2.y + bias[5];
        v1.z = c3.x + bias[6]; v1.w = c3.y + bias[7];
        *(float4*)(g_xg + o)     = v0;
        *(float4*)(g_xg + o + 4) = v1;
    }
}

// ---------------------------------------------------------------------------
// Phase 2: persistent recurrent kernel, FFMA2 + k-split microtiles.
// CTA owns 8 hidden units -> 32 gate rows (gate-major r = q*8+jj), 32 batches.
// Thread (ks, rg, bg): k-slice ks (256 k), rows 4rg..4rg+3, batches 4bg..4bg+3.
// ---------------------------------------------------------------------------
#define HP    36                         // hsm row pad (floats), 144B, 16B-aligned
#define SM_W  (1024 * 32)                // Wsm[k][r]
#define SM_H  (2 * 4 * 64 * HP)          // hsm[buf][ks][kk][b]
#define SM_P  (4 * 32 * 33)              // psm[ks][r][b]
#define SM_C  (8 * 33)                   // csm[j][b]
#define SMEM_REC ((SM_W + SM_H + SM_P + SM_C) * sizeof(float))

__global__ __launch_bounds__(256, 1) void lstm_rec_kernel(
    const float* __restrict__ Whh, const float* __restrict__ c0)
{
    extern __shared__ float sm[];
    float* Wsm = sm;                 // [1024][32]
    float* hsm = sm + SM_W;          // [2][4][64][HP]
    float* psm = hsm + SM_H;         // [4][32][33]
    float* csm = psm + SM_P;         // [8][33]

    const int tid = threadIdx.x;
    const int j0  = blockIdx.x * 8;

    // Load W_hh slice once (coalesced over k)
    for (int idx = tid; idx < 32 * 1024; idx += 256) {
        int r = idx >> 10, k = idx & 1023;
        int q = r >> 3, jj = r & 7;
        Wsm[k * 32 + r] = Whh[(size_t)(q * HID_ + j0 + jj) * HID_ + k];
    }
    const int je = tid & 7, be = tid >> 3;
    csm[je * 33 + be] = c0[be * HID_ + j0 + je];
    __syncthreads();

    // compute mapping
    const int ks  = tid >> 6;
    const int rg4 = ((tid >> 3) & 7) * 4;
    const int bg4 = (tid & 7) * 4;
    // staging mapping: unit u = i*256 + tid; kkg_lo=tid[1:0], b=tid[6:2],
    // hi = u>>7 -> ks2=hi>>2, kkg_hi=hi&3
    const int st_klo = tid & 3;
    const int st_b   = (tid >> 2) & 31;
    const int st_hi0 = tid >> 7;

    for (int t = 0; t < T_; ++t) {
        const float* hg = g_h[t & 1];
        float*       hw = g_h[(t & 1) ^ 1];

        // prefetch xg for this thread's cell-phase element (latency hidden by k loop)
        const size_t mb = (((size_t)be * T_ + t) << 12) + j0 + je;
        float xg0 = __ldcg(g_xg + mb);
        float xg1 = __ldcg(g_xg + mb + 1024);
        float xg2 = __ldcg(g_xg + mb + 2048);
        float xg3 = __ldcg(g_xg + mb + 3072);

        // stage chunk 0 -> buf 0
        #pragma unroll
        for (int i = 0; i < 8; ++i) {
            int hi  = i * 2 + st_hi0;              // 0..15
            int ks2 = hi >> 2, kkg = st_klo | ((hi & 3) << 2);
            float4 v = __ldcg((const float4*)(hg + st_b * HID_ + ks2 * 256 + kkg * 4));
            float* d = hsm + (ks2 * 64 + kkg * 4) * HP + st_b;
            d[0] = v.x; d[HP] = v.y; d[2 * HP] = v.z; d[3 * HP] = v.w;
        }

        ull acc[4][2];
        #pragma unroll
        for (int i = 0; i < 4; ++i) { acc[i][0] = 0ull; acc[i][1] = 0ull; }

        #pragma unroll 1
        for (int c = 0; c < 4; ++c) {
            __syncthreads();
            if (c < 3) {
                float* base = hsm + (((c + 1) & 1) * 4) * 64 * HP;
                const int kb = (c + 1) * 64;
                #pragma unroll
                for (int i = 0; i < 8; ++i) {
                    int hi  = i * 2 + st_hi0;
                    int ks2 = hi >> 2, kkg = st_klo | ((hi & 3) << 2);
                    float4 v = __ldcg((const float4*)(hg + st_b * HID_ + ks2 * 256 + kb + kkg * 4));
                    float* d = base + (ks2 * 64 + kkg * 4) * HP + st_b;
                    d[0] = v.x; d[HP] = v.y; d[2 * HP] = v.z; d[3 * HP] = v.w;
                }
            }
            const float* wp = Wsm + (ks * 256 + c * 64) * 32 + rg4;
            const float* hp = hsm + (((c & 1) * 4 + ks) * 64) * HP + bg4;
            #pragma unroll 8
            for (int kk = 0; kk < 64; ++kk) {
                float4 w = *(const float4*)(wp + kk * 32);
                ulonglong2 hv = *(const ulonglong2*)(hp + kk * HP);  // (h0,h1),(h2,h3)
                ull p0 = pack2(w.x), p1 = pack2(w.y), p2 = pack2(w.z), p3 = pack2(w.w);
                ffma2(acc[0][0], p0, hv.x); ffma2(acc[0][1], p0, hv.y);
                ffma2(acc[1][0], p1, hv.x); ffma2(acc[1][1], p1, hv.y);
                ffma2(acc[2][0], p2, hv.x); ffma2(acc[2][1], p2, hv.y);
                ffma2(acc[3][0], p3, hv.x); ffma2(acc[3][1], p3, hv.y);
            }
        }
        __syncthreads();

        // write k-slice partials
        #pragma unroll
        for (int i = 0; i < 4; ++i) {
            float2 lo = unpack2(acc[i][0]);
            float2 hi = unpack2(acc[i][1]);
            float* pr = psm + (ks * 32 + rg4 + i) * 33 + bg4;
            pr[0] = lo.x; pr[1] = lo.y; pr[2] = hi.x; pr[3] = hi.y;
        }
        __syncthreads();

        // cell update: thread (je, be)
        {
            float gi = 0.f, gf = 0.f, gg = 0.f, go = 0.f;
            #pragma unroll
            for (int s = 0; s < 4; ++s) {
                gi += psm[(s * 32 +  0 + je) * 33 + be];
                gf += psm[(s * 32 +  8 + je) * 33 + be];
                gg += psm[(s * 32 + 16 + je) * 33 + be];
                go += psm[(s * 32 + 24 + je) * 33 + be];
            }
            float pi = gi + xg0, pf = gf + xg1, pg = gg + xg2, po = go + xg3;
            float ig = 1.0f / (1.0f + expf(-pi));
            float fg = 1.0f / (1.0f + expf(-pf));
            float gt = tanhf(pg);
            float og = 1.0f / (1.0f + expf(-po));
            float cn = fmaf(fg, csm[je * 33 + be], ig * gt);
            csm[je * 33 + be] = cn;
            hw[be * HID_ + j0 + je] = og * tanhf(cn);
        }
        grid_barrier(NCTA);
    }
    // final h (t=511 odd) lands in g_h[0]
}

__global__ void copy_out_kernel(float* __restrict__ out) {
    int i = blockIdx.x * blockDim.x + threadIdx.x;
    if (i < B_ * HID_) out[i] = g_h[0][i];
}

// ---------------------------------------------------------------------------
// launch
// ---------------------------------------------------------------------------
extern "C" void kernel_launch(void* const* d_in, const int* in_sizes, int n_in,
                              void* d_out, int out_size) {
    const float* x   = (const float*)d_in[0];
    const float* h0  = (const float*)d_in[1];
    const float* c0  = (const float*)d_in[2];
    const float* Wih = (const float*)d_in[3];
    const float* Whh = (const float*)d_in[4];
    const float* bih = (const float*)d_in[5];
    const float* bhh = (const float*)d_in[6];
    float* out = (float*)d_out;

    cudaFuncSetAttribute(lstm_rec_kernel,
                         cudaFuncAttributeMaxDynamicSharedMemorySize,
                         (int)SMEM_REC);

    init_h_kernel<<<32, 1024>>>(h0);

    dim3 grid(G4 / BN, (B_ * T_) / BM);   // 32 x 128
    xg_gemm_kernel<<<grid, 256>>>(x, Wih, bih, bhh);

    lstm_rec_kernel<<<NCTA, 256, SMEM_REC>>>(Whh, c0);

    copy_out_kernel<<<32, 1024>>>(out);
}